// round 15
// baseline (speedup 1.0000x reference)
#include <cuda_runtime.h>
#include <math.h>

#define DPI 3.14159265358979323846

#define NB   128
#define NIN  30
#define BB1  10
#define MM1  19
#define NA1  20
#define FF1  20
#define BB2  6
#define MM2  11
#define NA2  12
#define FF2  40
#define FOUT 10
#define P1   24
#define P2   144

// ---- constant tables ----
__device__ float  gWS2F[BB1*MM1*NIN];
__device__ float2 gT1t[NIN*NIN*BB1*MM1];
__device__ float2 gBS2[P1*BB1*MM1];
__device__ float  gWINV1[NA1*BB1*MM1*MM1];
__device__ float2 gEA1[MM1*NA1];
__device__ float  gWSO3[NA1*BB2*MM2*MM2];
__device__ float2 gF20[MM2*NA1];
__device__ float2 gBSO3[P2*BB2*MM2*MM2];
__device__ float  gWINV2[NA2*BB2*MM2*MM2];
__device__ float2 gEA2[MM2*NA2];
__device__ float  gWINT[NA2];

// ---- init helper tables ----
__device__ float  gQW10[20];
__device__ float2 gPA8[8*19];
__device__ float2 gPA8b[8*11];
__device__ float2 gPG6[6*11];
__device__ float2 gPH30[19*30];
__device__ float  gDS2G[3*10*10];
__device__ float  gDG3[3*6*121];

// ---- scratch ----
#define XCH 10
#define XLEN 90
__device__ float2 gXpart[XCH][NB*BB1*MM1];
__device__ float2 gX   [NB*BB1*MM1];
__device__ float2 gPSI [FF1*BB1*MM1];
__device__ float2 gYMN [NB*FF1*NA1*MM2*MM2];   // only mu>=5 rows written/read
__device__ float2 gX2  [NB*FF1*BB2*MM2*MM2];   // only m>=5 rows written/read
__device__ float2 gPSI2[FF1*FF2*BB2*MM2*MM2];
__device__ float2 gZ2  [NB*FF2*BB2*MM2*MM2];   // m<center & invalid entries never read
__device__ float  gFEAT[NB*FF2];

__device__ __constant__ double c_fact[21] = {
  1.0, 1.0, 2.0, 6.0, 24.0, 120.0, 720.0, 5040.0, 40320.0, 362880.0,
  3628800.0, 39916800.0, 479001600.0, 6227020800.0, 87178291200.0,
  1307674368000.0, 20922789888000.0, 355687428096000.0,
  6402373705728000.0, 121645100408832000.0, 2432902008176640000.0 };

__device__ __forceinline__ double ipowd(double x, int e) {
  double r = 1.0;
  for (int i = 0; i < e; ++i) r *= x;
  return r;
}

__device__ double wigd(int l, int m, int n, double beta) {
  double cb = cos(0.5 * beta), sb = sin(0.5 * beta);
  double pref = sqrt(c_fact[l+m] * c_fact[l-m] * c_fact[l+n] * c_fact[l-n]);
  int s0 = (n - m > 0) ? (n - m) : 0;
  int s1 = (l + n < l - m) ? (l + n) : (l - m);
  double v = 0.0;
  for (int s = s0; s <= s1; ++s) {
    double t = 1.0 / (c_fact[l+n-s] * c_fact[s] * c_fact[m-n+s] * c_fact[l-m-s]);
    if ((m - n + s) & 1) t = -t;
    v += t * ipowd(cb, 2*l + n - m - 2*s) * ipowd(sb, m - n + 2*s);
  }
  return pref * v;
}

__device__ double quadw(int b, int k) {
  double beta = DPI * (2*k + 1) / (4.0 * b);
  double s = 0.0;
  for (int j = 0; j < b; ++j) s += sin((2*j + 1) * beta) / (2*j + 1);
  return 2.0 / b * sin(beta) * s;
}

// ======================= init =======================
__global__ void k_init_wig() {
  int idx = blockIdx.x * blockDim.x + threadIdx.x;
  if (idx < 20) { gQW10[idx] = (float)quadw(10, idx); return; }
  idx -= 20;
  if (idx < 12) { gWINT[idx] = (float)quadw(6, idx); return; }
  idx -= 12;
  if (idx < 152) {
    int ia = idx / 19, mp = idx % 19 - 9;
    double ph = -(double)mp * (2.0 * DPI * ia / 8.0);
    double s, c; sincos(ph, &s, &c);
    gPA8[idx] = make_float2((float)c, (float)s); return;
  }
  idx -= 152;
  if (idx < 88) {
    int ia = idx / 11, mp = idx % 11 - 5;
    double ph = -(double)mp * (2.0 * DPI * ia / 8.0);
    double s, c; sincos(ph, &s, &c);
    gPA8b[idx] = make_float2((float)c, (float)s); return;
  }
  idx -= 88;
  if (idx < 66) {
    int ig = idx / 11, np = idx % 11 - 5;
    double ph = -(double)np * (2.0 * DPI * ig / 6.0);
    double s, c; sincos(ph, &s, &c);
    gPG6[idx] = make_float2((float)c, (float)s); return;
  }
  idx -= 66;
  if (idx < 570) {
    int mp = idx / 30 - 9, j = idx % 30;
    double ph = -2.0 * DPI * (double)mp * j / 30.0;
    double s, c; sincos(ph, &s, &c);
    gPH30[idx] = make_float2((float)c, (float)s); return;
  }
  idx -= 570;
  if (idx < 380) {
    int m = idx / 20 - 9, a = idx % 20;
    double ph = (double)m * 2.0 * DPI * a / 20.0;
    double s, c; sincos(ph, &s, &c);
    gEA1[idx] = make_float2((float)c, (float)s); return;
  }
  idx -= 380;
  if (idx < 132) {
    int m = idx / 12 - 5, a = idx % 12;
    double ph = (double)m * 2.0 * DPI * a / 12.0;
    double s, c; sincos(ph, &s, &c);
    gEA2[idx] = make_float2((float)c, (float)s); return;
  }
  idx -= 132;
  if (idx < 220) {
    int mu = idx / 20 - 5, a = idx % 20;
    double ph = -2.0 * DPI * (double)mu * a / 20.0;
    double s, c; sincos(ph, &s, &c);
    gF20[idx] = make_float2((float)c, (float)s); return;
  }
  idx -= 220;
  if (idx < 1650) {
    int kb = idx / 55, j = idx % 55;
    int l = 0; while (j >= l + 1) { j -= l + 1; ++l; }
    int mm = j;
    double beta = DPI * (2*kb + 1) / 60.0;
    double v = wigd(l, mm, 0, beta) * quadw(15, kb);
    gWS2F[(l*19 + 9 + mm)*30 + kb] = (float)v;
    gWS2F[(l*19 + 9 - mm)*30 + kb] = (mm & 1) ? (float)(-v) : (float)v;
    return;
  }
  idx -= 1650;
  if (idx < 165) {
    int ib = idx / 55, j = idx % 55;
    int l = 0; while (j >= l + 1) { j -= l + 1; ++l; }
    int mm = j;
    double beta = (ib + 1) * DPI / 24.0;
    gDS2G[(ib*10 + l)*10 + mm] = (float)wigd(l, mm, 0, beta);
    return;
  }
  idx -= 165;
  if (idx < 7700) {
    int k = idx / 385, j = idx % 385;
    int l = 0; while (j >= (l+1)*(l+1)) { j -= (l+1)*(l+1); ++l; }
    int mm = (int)sqrtf((float)j);
    while (mm*mm > j) --mm;
    while ((mm+1)*(mm+1) <= j) ++mm;
    int nn = j - mm*mm - mm;
    double beta = DPI * (2*k + 1) / 40.0;
    float fv = (float)(wigd(l, mm, nn, beta) * (2*l + 1));
    float sv = ((mm - nn) & 1) ? -fv : fv;
    float* W = &gWINV1[(k*10 + l)*361];
    W[(9+mm)*19 + (9+nn)] = fv;
    W[(9+nn)*19 + (9+mm)] = sv;
    W[(9-mm)*19 + (9-nn)] = sv;
    W[(9-nn)*19 + (9-mm)] = fv;
    return;
  }
  idx -= 7700;
  if (idx < 1092) {
    int k = idx / 91, j = idx % 91;
    int l = 0; while (j >= (l+1)*(l+1)) { j -= (l+1)*(l+1); ++l; }
    int mm = (int)sqrtf((float)j);
    while (mm*mm > j) --mm;
    while ((mm+1)*(mm+1) <= j) ++mm;
    int nn = j - mm*mm - mm;
    double beta = DPI * (2*k + 1) / 24.0;
    float fv = (float)(wigd(l, mm, nn, beta) * (2*l + 1));
    float sv = ((mm - nn) & 1) ? -fv : fv;
    float* W = &gWINV2[(k*6 + l)*121];
    W[(5+mm)*11 + (5+nn)] = fv;
    W[(5+nn)*11 + (5+mm)] = sv;
    W[(5-mm)*11 + (5-nn)] = sv;
    W[(5-nn)*11 + (5-mm)] = fv;
    return;
  }
  idx -= 1092;
  if (idx < 273) {
    int ib = idx / 91, j = idx % 91;
    int l = 0; while (j >= (l+1)*(l+1)) { j -= (l+1)*(l+1); ++l; }
    int mm = (int)sqrtf((float)j);
    while (mm*mm > j) --mm;
    while ((mm+1)*(mm+1) <= j) ++mm;
    int nn = j - mm*mm - mm;
    double beta = (ib + 1) * DPI / 24.0;
    float fv = (float)wigd(l, mm, nn, beta);
    float sv = ((mm - nn) & 1) ? -fv : fv;
    float* W = &gDG3[(ib*6 + l)*121];
    W[(5+mm)*11 + (5+nn)] = fv;
    W[(5+nn)*11 + (5+mm)] = sv;
    W[(5-mm)*11 + (5-nn)] = sv;
    W[(5-nn)*11 + (5-mm)] = fv;
  }
}

__global__ void k_init_fill() {
  const int TOT = 4560 + 14520 + 104544 + 171000;
  for (int idx = blockIdx.x * blockDim.x + threadIdx.x; idx < TOT;
       idx += gridDim.x * blockDim.x) {
    int r = idx;
    if (r < 4560) {
      int p = r / 190, lm = r % 190, l = lm / 19, m = lm % 19, mp = m - 9;
      float2 v = make_float2(0.f, 0.f);
      if (abs(mp) <= l) {
        int ib = p / 8, ia = p % 8;
        float d;
        if (mp >= 0) d = gDS2G[(ib*10 + l)*10 + mp];
        else {
          d = gDS2G[(ib*10 + l)*10 - mp];
          if ((-mp) & 1) d = -d;
        }
        float2 ph = gPA8[ia*19 + 9 + mp];
        v = make_float2(d * ph.x, d * ph.y);
      }
      gBS2[r] = v; continue;
    }
    r -= 4560;
    if (r < 14520) {
      int k = r / 726, l = (r / 121) % 6, m = (r / 11) % 11, n = r % 11;
      float w = gWINV1[(k*10 + l)*361 + (m + 4)*19 + (n + 4)];
      gWSO3[r] = w * gQW10[k] / (float)(2*l + 1); continue;
    }
    r -= 14520;
    if (r < 104544) {
      int p = r / 726, l = (r / 121) % 6, m = (r / 11) % 11, n = r % 11;
      int ib = p / 48, ia = (p / 6) % 8, ig = p % 6;
      float d = gDG3[(ib*6 + l)*121 + m*11 + n];
      float2 pa = gPA8b[ia*11 + m], pg = gPG6[ig*11 + n];
      float2 ph = make_float2(pa.x*pg.x - pa.y*pg.y, pa.x*pg.y + pa.y*pg.x);
      gBSO3[r] = make_float2(d * ph.x, d * ph.y); continue;
    }
    r -= 104544;
    {
      int lm = r / 900, kj = r % 900;
      int k = kj / 30, j = kj % 30;
      int mp = (lm % 19) - 9;
      float w = gWS2F[lm*30 + k];
      float2 ph = gPH30[(mp + 9)*30 + j];
      gT1t[kj*190 + lm] = make_float2(w * ph.x, w * ph.y);
    }
  }
}

// ======================= pipeline =======================
__global__ void k_x_part(const float* __restrict__ x) {
  __shared__ float xs[XLEN];
  int blk = blockIdx.x;
  int c = blk % XCH, b = blk / XCH;
  for (int i = threadIdx.x; i < XLEN; i += blockDim.x) xs[i] = x[b*900 + c*XLEN + i];
  __syncthreads();
  int t = threadIdx.x;
  if (t < 190) {
    float re = 0.f, im = 0.f;
    const float2* T = &gT1t[c * XLEN * 190];
#pragma unroll 5
    for (int i = 0; i < XLEN; ++i) {
      float xv = xs[i];
      float2 w = T[i * 190 + t];
      re += xv * w.x; im += xv * w.y;
    }
    gXpart[c][b*190 + t] = make_float2(re, im);
  }
}

__global__ void k_comb_psi(const float* __restrict__ k1) {
  int idx = blockIdx.x * blockDim.x + threadIdx.x;
  if (idx < NB*190) {
    float re = 0.f, im = 0.f;
#pragma unroll
    for (int c = 0; c < XCH; ++c) {
      float2 v = gXpart[c][idx];
      re += v.x; im += v.y;
    }
    gX[idx] = make_float2(re, im);
    return;
  }
  idx -= NB*190;
  if (idx < FF1*190) {
    int lm = idx % 190, o = idx / 190;
    float re = 0.f, im = 0.f;
    for (int p = 0; p < P1; ++p) {
      float kv = k1[o*P1 + p];
      float2 bv = gBS2[p*190 + lm];
      re += kv * bv.x; im += kv * bv.y;
    }
    gPSI[idx] = make_float2(re, im);
  }
}

// ---- fused stage 1: 5 k/block, folds + register-cached DFT (R13 form) ----
__global__ __launch_bounds__(256) void k_fused1() {
  __shared__ float2 sX[190];
  __shared__ float2 sP[190];
  __shared__ float2 sEA1[380];
  __shared__ float2 sF20[220];
  __shared__ float2 sFH[950];
  __shared__ float2 sT[1000];
  __shared__ float  sY[2000];
  __shared__ float2 sU[600];

  int blk = blockIdx.x;                 // (b*FF1 + o)*4 + kp
  int kp = blk % 4;
  int bo = blk / 4;
  int o = bo % FF1, b = bo / FF1;
  int k0 = kp * 5;
  int tid = threadIdx.x;

  for (int e = tid; e < 190; e += 256) { sX[e] = gX[b*190 + e]; sP[e] = gPSI[o*190 + e]; }
  for (int e = tid; e < 380; e += 256) sEA1[e] = gEA1[e];
  for (int e = tid; e < 220; e += 256) sF20[e] = gF20[e];
  __syncthreads();

  for (int e = tid; e < 950; e += 256) {
    int sk = e / 190, r = e % 190;
    int mi = r / 19, n = r % 19;
    int an = n - 9; if (an < 0) an = -an;
    int lmin = mi > an ? mi : an;
    const float* W = &gWINV1[(k0 + sk) * BB1 * 361];
    int off = (9 + mi)*19 + n;
    float re = 0.f, im = 0.f;
    for (int l = lmin; l < BB1; ++l) {
      float w = W[l*361 + off];
      float2 xm = sX[l*19 + 9 + mi];
      float2 pe = sP[l*19 + n];
      re += w * (xm.x * pe.x + xm.y * pe.y);
      im += w * (xm.y * pe.x - xm.x * pe.y);
    }
    sFH[e] = make_float2(re, im);
  }
  __syncthreads();

  if (tid < 250) {
    int sk = tid / 50, rem = tid % 50;
    int mi = rem / 5, gq = rem % 5;
    float2 f[19];
#pragma unroll
    for (int n = 0; n < 19; ++n) f[n] = sFH[sk*190 + mi*19 + n];
#pragma unroll
    for (int dg = 0; dg < 2; ++dg) {
      int g = gq*2 + dg;
      float sex = 0.f, sey = 0.f, sox = 0.f, soy = 0.f;
#pragma unroll
      for (int n = 0; n < 19; ++n) {
        float2 ea = sEA1[n*20 + g];
        float tx = f[n].x * ea.x - f[n].y * ea.y;
        float ty = f[n].x * ea.y + f[n].y * ea.x;
        if (n & 1) { sex += tx; sey += ty; }
        else       { sox += tx; soy += ty; }
      }
      sT[sk*200 + mi*20 + g]      = make_float2(sex + sox, sey + soy);
      sT[sk*200 + mi*20 + g + 10] = make_float2(sex - sox, sey - soy);
    }
  }
  __syncthreads();

  if (tid < 200) {
    int sk = tid / 40, rem = tid % 40;
    int g = rem / 2, ah = rem % 2;
    float t0 = sT[sk*200 + g].x;
    float2 tm[9];
#pragma unroll
    for (int mm = 1; mm < 10; ++mm) tm[mm-1] = sT[sk*200 + mm*20 + g];
    int a0 = ah * 5;
#pragma unroll
    for (int da = 0; da < 5; ++da) {
      int a = a0 + da;
      float se = 0.f, so = 0.f;
#pragma unroll
      for (int mm = 1; mm < 10; ++mm) {
        float2 ea = sEA1[(9 + mm)*20 + a];
        float v = tm[mm-1].x * ea.x - tm[mm-1].y * ea.y;
        if (mm & 1) so += v; else se += v;
      }
      float y1 = t0 + 2.f * (se + so);
      float y2v = t0 + 2.f * (se - so);
      y1 = (y1 > 0.f) ? y1 : 0.f;
      y2v = (y2v > 0.f) ? y2v : 0.f;
      sY[sk*400 + a*20 + g]      = y1 + y2v;
      sY[sk*400 + (a+10)*20 + g] = y1 - y2v;
    }
  }
  __syncthreads();

  if (tid < 100) {
    int sk = tid / 20, g = tid % 20;
    float ys[10], yd[10];
#pragma unroll
    for (int a = 0; a < 10; ++a) {
      ys[a] = sY[sk*400 + a*20 + g];
      yd[a] = sY[sk*400 + (a+10)*20 + g];
    }
#pragma unroll
    for (int r = 0; r < 6; ++r) {
      const float* yb = (r & 1) ? yd : ys;
      float re = 0.f, im = 0.f;
#pragma unroll
      for (int a = 0; a < 10; ++a) {
        float2 fw = sF20[(5 + r)*20 + a];
        re += yb[a] * fw.x; im += yb[a] * fw.y;
      }
      sU[sk*120 + r*20 + g] = make_float2(re, im);
    }
  }
  __syncthreads();

  // ymn wedge only (mu >= 5); mirror write dropped (dead downstream)
  for (int e = tid; e < 330; e += 256) {
    int sk = e / 66, rr = e % 66;
    int r = rr / 11, nu = rr % 11;
    float sgn = (nu & 1) ? 1.f : -1.f;
    float re = 0.f, im = 0.f;
#pragma unroll
    for (int g = 0; g < 10; ++g) {
      float2 u1 = sU[sk*120 + r*20 + g];
      float2 u2 = sU[sk*120 + r*20 + g + 10];
      float ux = u1.x + sgn * u2.x;
      float uy = u1.y + sgn * u2.y;
      float2 f = sF20[nu*20 + g];
      re += ux * f.x - uy * f.y;
      im += ux * f.y + uy * f.x;
    }
    long yb = ((long)bo * 20 + k0 + sk) * 121;
    gYMN[yb + (5 + r)*11 + nu] = make_float2(re, im);
  }
}

// X2 wedge: one thread per (b,c,we), we over mu=5..10 x nu=0..10 (66 positions).
__global__ void k_x2() {
  int idx = blockIdx.x * blockDim.x + threadIdx.x;
  if (idx >= NB*FF1*66) return;
  int we = idx % 66, bc = idx / 66;
  int mn = (5 + we / 11)*11 + (we % 11);
  float2 ym[20];
  long ybase = (long)bc * 20 * 121 + mn;
#pragma unroll
  for (int k = 0; k < 20; ++k) ym[k] = gYMN[ybase + k*121];
  long xbase = (long)bc * 726 + mn;
#pragma unroll
  for (int l = 0; l < BB2; ++l) {
    float re = 0.f, im = 0.f;
#pragma unroll
    for (int k = 0; k < 20; ++k) {
      float w = gWSO3[(k*6 + l)*121 + mn];
      re += w * ym[k].x; im += w * ym[k].y;
    }
    gX2[xbase + l*121] = make_float2(re, im);
  }
}

// psi2 as real x complex GEMM: (800 x 144) x (144 x 726)
__global__ void k_psi2(const float* __restrict__ k2) {
  const int M = 800, N = 726, K = 144;
  __shared__ float As[32][17];
  __shared__ __align__(16) float2 Bs[16][34];
  int tx = threadIdx.x, ty = threadIdx.y;
  int tid = ty * 16 + tx;
  int row0 = blockIdx.y * 32, col0 = blockIdx.x * 32;
  float2 c00 = {0.f,0.f}, c01 = {0.f,0.f}, c10 = {0.f,0.f}, c11 = {0.f,0.f};

  for (int kt = 0; kt < K; kt += 16) {
#pragma unroll
    for (int e = tid; e < 512; e += 256) {
      int i = e >> 4, kq = e & 15;
      int row = row0 + i, kc = kt + kq;
      As[i][kq] = (row < M) ? k2[row*K + kc] : 0.f;
    }
#pragma unroll
    for (int e = tid; e < 512; e += 256) {
      int kq = e >> 5, j = e & 31;
      int kc = kt + kq, col = col0 + j;
      Bs[kq][j] = (col < N) ? gBSO3[kc*726 + col] : make_float2(0.f, 0.f);
    }
    __syncthreads();
#pragma unroll
    for (int kq = 0; kq < 16; ++kq) {
      float a0 = As[ty*2][kq];
      float a1 = As[ty*2 + 1][kq];
      float4 bb = *reinterpret_cast<const float4*>(&Bs[kq][tx*2]);
      c00.x += a0*bb.x; c00.y += a0*bb.y;
      c01.x += a0*bb.z; c01.y += a0*bb.w;
      c10.x += a1*bb.x; c10.y += a1*bb.y;
      c11.x += a1*bb.z; c11.y += a1*bb.w;
    }
    __syncthreads();
  }
  int r0 = row0 + ty*2, cc0 = col0 + tx*2;
  if (r0 < M) {
    if (cc0 < N)     gPSI2[r0*726 + cc0] = c00;
    if (cc0 + 1 < N) gPSI2[r0*726 + cc0 + 1] = c01;
  }
  if (r0 + 1 < M) {
    if (cc0 < N)     gPSI2[(r0+1)*726 + cc0] = c10;
    if (cc0 + 1 < N) gPSI2[(r0+1)*726 + cc0 + 1] = c11;
  }
}

// Z2 complex GEMM per l; rows restricted to m >= center.
__global__ void k_z2() {
  int l = blockIdx.z;
  int D = 2*l + 1;
  int E = l + 1;
  int R = 128*E, C = 40*D, K = 20*D;
  int row0 = blockIdx.y * 32, col0 = blockIdx.x * 64;
  if (row0 >= R || col0 >= C) return;
  __shared__ __align__(16) float2 As[32][17];
  __shared__ __align__(16) float2 Bs[16][66];
  __shared__ int sRA[32];
  __shared__ int sCB[64];
  __shared__ int sRO[32];
  __shared__ int sCO[64];
  __shared__ int sKA[220];
  __shared__ int sKB[220];
  int tx = threadIdx.x, ty = threadIdx.y;
  int tid = ty * 16 + tx;
  int base = 5 - l;
  int L0 = l*121 + base*12;

  for (int e = tid; e < 32; e += 256) {
    int row = row0 + e;
    if (row < R) {
      int b = row / E, mi = row - b*E;
      int rp = l*121 + (5 + mi)*11 + base;
      sRA[e] = b*14520 + rp;
      sRO[e] = b*29040 + rp;
    } else { sRA[e] = -1; sRO[e] = -1; }
  }
  for (int e = tid; e < 64; e += 256) {
    int col = col0 + e;
    if (col < C) {
      int o = col / D, ni = col - o*D;
      sCB[e] = o*726 + ni*11 + L0;
      sCO[e] = o*726 + ni;
    } else { sCB[e] = -1; sCO[e] = -1; }
  }
  for (int e = tid; e < K; e += 256) {
    int ii = e / D, ki = e - ii*D;
    sKA[e] = ii*726 + ki;
    sKB[e] = ii*29040 + ki;
  }
  __syncthreads();

  float2 acc[2][4];
#pragma unroll
  for (int i = 0; i < 2; ++i)
#pragma unroll
    for (int j = 0; j < 4; ++j) acc[i][j] = make_float2(0.f, 0.f);

  for (int kt = 0; kt < K; kt += 16) {
#pragma unroll
    for (int e = tid; e < 512; e += 256) {
      int i = e >> 4, kq = e & 15;
      int kc = kt + kq;
      float2 v = make_float2(0.f, 0.f);
      if (kc < K && sRA[i] >= 0) v = gX2[sRA[i] + sKA[kc]];
      As[i][kq] = v;
    }
#pragma unroll
    for (int e = tid; e < 1024; e += 256) {
      int kq = e >> 6, j = e & 63;
      int kc = kt + kq;
      float2 v = make_float2(0.f, 0.f);
      if (kc < K && sCB[j] >= 0) v = gPSI2[sCB[j] + sKB[kc]];
      Bs[kq][j] = v;
    }
    __syncthreads();
#pragma unroll
    for (int kq = 0; kq < 16; ++kq) {
      float2 a0 = As[ty*2][kq];
      float2 a1 = As[ty*2 + 1][kq];
      float4 b0 = *reinterpret_cast<const float4*>(&Bs[kq][tx*2]);
      float4 b1 = *reinterpret_cast<const float4*>(&Bs[kq][tx*2 + 32]);
      acc[0][0].x += a0.x*b0.x + a0.y*b0.y;  acc[0][0].y += a0.y*b0.x - a0.x*b0.y;
      acc[0][1].x += a0.x*b0.z + a0.y*b0.w;  acc[0][1].y += a0.y*b0.z - a0.x*b0.w;
      acc[0][2].x += a0.x*b1.x + a0.y*b1.y;  acc[0][2].y += a0.y*b1.x - a0.x*b1.y;
      acc[0][3].x += a0.x*b1.z + a0.y*b1.w;  acc[0][3].y += a0.y*b1.z - a0.x*b1.w;
      acc[1][0].x += a1.x*b0.x + a1.y*b0.y;  acc[1][0].y += a1.y*b0.x - a1.x*b0.y;
      acc[1][1].x += a1.x*b0.z + a1.y*b0.w;  acc[1][1].y += a1.y*b0.z - a1.x*b0.w;
      acc[1][2].x += a1.x*b1.x + a1.y*b1.y;  acc[1][2].y += a1.y*b1.x - a1.x*b1.y;
      acc[1][3].x += a1.x*b1.z + a1.y*b1.w;  acc[1][3].y += a1.y*b1.z - a1.x*b1.w;
    }
    __syncthreads();
  }

  int ir0 = ty*2;
  int jc[4] = { tx*2, tx*2 + 1, tx*2 + 32, tx*2 + 33 };
#pragma unroll
  for (int dr = 0; dr < 2; ++dr) {
    int ro = sRO[ir0 + dr];
    if (ro < 0) continue;
#pragma unroll
    for (int dc = 0; dc < 4; ++dc) {
      int co = sCO[jc[dc]];
      if (co < 0) continue;
      gZ2[ro + co] = acc[dr][dc];
    }
  }
}

// ---- fused stage 2: wedge-only sZ loads, hermitian + folds ----
__global__ __launch_bounds__(256) void k_fused2() {
  __shared__ float2 sZw[396];     // [l][mi][n], m = 5+mi
  __shared__ float2 sFH2[792];
  __shared__ float2 sT2[864];
  __shared__ float2 sEA2[132];
  __shared__ float  sRed[256];

  int blk = blockIdx.x;
  int tid = threadIdx.x;

  for (int e = tid; e < 396; e += 256) {
    int l = e / 66, rr = e % 66;
    sZw[e] = gZ2[(long)blk * 726 + l*121 + (5 + rr/11)*11 + (rr % 11)];
  }
  for (int e = tid; e < 132; e += 256) sEA2[e] = gEA2[e];
  __syncthreads();

  for (int e = tid; e < 792; e += 256) {
    int k = e / 66, rem = e % 66;
    int mi = rem / 11, n = rem % 11;
    int an = n - 5; if (an < 0) an = -an;
    int lmin = mi > an ? mi : an;
    float re = 0.f, im = 0.f;
    for (int l = lmin; l < BB2; ++l) {
      float w = gWINV2[(k*6 + l)*121 + (5 + mi)*11 + n];
      float2 z = sZw[l*66 + mi*11 + n];
      re += w * z.x; im += w * z.y;
    }
    sFH2[e] = make_float2(re, im);
  }
  __syncthreads();

  for (int e = tid; e < 216; e += 256) {
    int k = e / 18, rr = e % 18;
    int mi = rr / 3, gh = rr % 3;
    float2 f[11];
#pragma unroll
    for (int n = 0; n < 11; ++n) f[n] = sFH2[(k*6 + mi)*11 + n];
#pragma unroll
    for (int dg = 0; dg < 2; ++dg) {
      int g = gh*2 + dg;
      float sex = 0.f, sey = 0.f, sox = 0.f, soy = 0.f;
#pragma unroll
      for (int n = 0; n < 11; ++n) {
        float2 ea = sEA2[n*12 + g];
        float tx = f[n].x * ea.x - f[n].y * ea.y;
        float ty = f[n].x * ea.y + f[n].y * ea.x;
        if (n & 1) { sex += tx; sey += ty; }
        else       { sox += tx; soy += ty; }
      }
      sT2[(k*6 + mi)*12 + g]     = make_float2(sex + sox, sey + soy);
      sT2[(k*6 + mi)*12 + g + 6] = make_float2(sex - sox, sey - soy);
    }
  }
  __syncthreads();

  float partial = 0.f;
  for (int e = tid; e < 144; e += 256) {
    int k = e / 12, g = e % 12;
    float t0 = sT2[k*72 + g].x;
    float2 tm[5];
#pragma unroll
    for (int mm = 1; mm < 6; ++mm) tm[mm-1] = sT2[(k*6 + mm)*12 + g];
    float wk = gWINT[k];
#pragma unroll
    for (int a = 0; a < 6; ++a) {
      float se = 0.f, so = 0.f;
#pragma unroll
      for (int mm = 1; mm < 6; ++mm) {
        float2 ea = sEA2[(5 + mm)*12 + a];
        float v = tm[mm-1].x * ea.x - tm[mm-1].y * ea.y;
        if (mm & 1) so += v; else se += v;
      }
      float v1 = t0 + 2.f * (se + so);
      float v2 = t0 + 2.f * (se - so);
      v1 = (v1 > 0.f) ? v1 : 0.f;
      v2 = (v2 > 0.f) ? v2 : 0.f;
      partial += (v1 + v2) * wk;
    }
  }
  sRed[tid] = partial;
  __syncthreads();
  for (int s = 128; s > 0; s >>= 1) {
    if (tid < s) sRed[tid] += sRed[tid + s];
    __syncthreads();
  }
  if (tid == 0) gFEAT[blk] = sRed[0] / 144.0f;
}

__global__ void k_out(const float* __restrict__ wl, const float* __restrict__ bl,
                      float* __restrict__ out) {
  int idx = blockIdx.x * blockDim.x + threadIdx.x;
  if (idx >= NB*FOUT) return;
  int f = idx % FOUT, b = idx / FOUT;
  float acc = bl[f];
#pragma unroll
  for (int o = 0; o < FF2; ++o) acc += gFEAT[b*FF2 + o] * wl[f*FF2 + o];
  out[idx] = acc;
}

extern "C" void kernel_launch(void* const* d_in, const int* in_sizes, int n_in,
                              void* d_out, int out_size) {
  const float* x  = (const float*)d_in[0];
  const float* k1 = (const float*)d_in[1];
  const float* k2 = (const float*)d_in[2];
  const float* wl = (const float*)d_in[3];
  const float* bl = (const float*)d_in[4];
  float* out = (float*)d_out;

  k_init_wig<<<(12520 + 255) / 256, 256>>>();
  k_init_fill<<<(294624 + 255) / 256, 256>>>();

  k_x_part<<<NB*XCH, 192>>>(x);
  k_comb_psi<<<(NB*190 + FF1*190 + 255) / 256, 256>>>(k1);
  k_fused1<<<NB*FF1*4, 256>>>();
  k_x2 <<<(NB*FF1*66 + 255) / 256, 256>>>();
  k_psi2<<<dim3((726 + 31) / 32, (800 + 31) / 32), dim3(16, 16)>>>(k2);
  k_z2<<<dim3(7, 24, 6), dim3(16, 16)>>>();
  k_fused2<<<NB*FF2, 256>>>();
  k_out<<<(NB*FOUT + 255) / 256, 256>>>(wl, bl, out);
}

// round 16
// speedup vs baseline: 1.6241x; 1.6241x over previous
#include <cuda_runtime.h>
#include <math.h>

#define DPI 3.14159265358979323846

#define NB   128
#define NIN  30
#define BB1  10
#define MM1  19
#define NA1  20
#define FF1  20
#define BB2  6
#define MM2  11
#define NA2  12
#define FF2  40
#define FOUT 10
#define P1   24
#define P2   144

// ---- constant tables ----
__device__ float  gWS2F[BB1*MM1*NIN];
__device__ float2 gT1t[NIN*NIN*BB1*MM1];
__device__ float2 gBS2[P1*BB1*MM1];
__device__ float  gWINV1[NA1*BB1*MM1*MM1];
__device__ float2 gEA1[MM1*NA1];
__device__ float  gWSO3[NA1*BB2*MM2*MM2];
__device__ float2 gF20[MM2*NA1];
__device__ float2 gBSO3[P2*BB2*MM2*MM2];
__device__ float  gWINV2[NA2*BB2*MM2*MM2];
__device__ float2 gEA2[MM2*NA2];
__device__ float  gWINT[NA2];

// ---- init helper tables ----
__device__ float  gQW10[20];
__device__ float2 gPA8[8*19];
__device__ float2 gPA8b[8*11];
__device__ float2 gPG6[6*11];
__device__ float2 gPH30[19*30];
__device__ float  gDS2G[3*10*10];
__device__ float  gDG3[3*6*121];

// ---- scratch ----
#define XCH 10
#define XLEN 90
__device__ float2 gXpart[XCH][NB*BB1*MM1];
__device__ float2 gX   [NB*BB1*MM1];
__device__ float2 gPSI [FF1*BB1*MM1];
__device__ float2 gYMN [NB*FF1*NA1*MM2*MM2];   // only mu>=5 rows written/read
__device__ float2 gX2  [NB*FF1*BB2*MM2*MM2];   // only m>=5 rows written/read
__device__ float2 gPSI2[FF1*FF2*BB2*MM2*MM2];
__device__ float2 gZ2  [NB*FF2*BB2*MM2*MM2];   // m<center & invalid entries never read
__device__ float  gFEAT[NB*FF2];

__device__ __constant__ double c_fact[21] = {
  1.0, 1.0, 2.0, 6.0, 24.0, 120.0, 720.0, 5040.0, 40320.0, 362880.0,
  3628800.0, 39916800.0, 479001600.0, 6227020800.0, 87178291200.0,
  1307674368000.0, 20922789888000.0, 355687428096000.0,
  6402373705728000.0, 121645100408832000.0, 2432902008176640000.0 };

__device__ __forceinline__ double ipowd(double x, int e) {
  double r = 1.0;
  for (int i = 0; i < e; ++i) r *= x;
  return r;
}

__device__ double wigd(int l, int m, int n, double beta) {
  double cb = cos(0.5 * beta), sb = sin(0.5 * beta);
  double pref = sqrt(c_fact[l+m] * c_fact[l-m] * c_fact[l+n] * c_fact[l-n]);
  int s0 = (n - m > 0) ? (n - m) : 0;
  int s1 = (l + n < l - m) ? (l + n) : (l - m);
  double v = 0.0;
  for (int s = s0; s <= s1; ++s) {
    double t = 1.0 / (c_fact[l+n-s] * c_fact[s] * c_fact[m-n+s] * c_fact[l-m-s]);
    if ((m - n + s) & 1) t = -t;
    v += t * ipowd(cb, 2*l + n - m - 2*s) * ipowd(sb, m - n + 2*s);
  }
  return pref * v;
}

__device__ double quadw(int b, int k) {
  double beta = DPI * (2*k + 1) / (4.0 * b);
  double s = 0.0;
  for (int j = 0; j < b; ++j) s += sin((2*j + 1) * beta) / (2*j + 1);
  return 2.0 / b * sin(beta) * s;
}

// ======================= init =======================
__global__ void k_init_wig() {
  int idx = blockIdx.x * blockDim.x + threadIdx.x;
  if (idx < 20) { gQW10[idx] = (float)quadw(10, idx); return; }
  idx -= 20;
  if (idx < 12) { gWINT[idx] = (float)quadw(6, idx); return; }
  idx -= 12;
  if (idx < 152) {
    int ia = idx / 19, mp = idx % 19 - 9;
    double ph = -(double)mp * (2.0 * DPI * ia / 8.0);
    double s, c; sincos(ph, &s, &c);
    gPA8[idx] = make_float2((float)c, (float)s); return;
  }
  idx -= 152;
  if (idx < 88) {
    int ia = idx / 11, mp = idx % 11 - 5;
    double ph = -(double)mp * (2.0 * DPI * ia / 8.0);
    double s, c; sincos(ph, &s, &c);
    gPA8b[idx] = make_float2((float)c, (float)s); return;
  }
  idx -= 88;
  if (idx < 66) {
    int ig = idx / 11, np = idx % 11 - 5;
    double ph = -(double)np * (2.0 * DPI * ig / 6.0);
    double s, c; sincos(ph, &s, &c);
    gPG6[idx] = make_float2((float)c, (float)s); return;
  }
  idx -= 66;
  if (idx < 570) {
    int mp = idx / 30 - 9, j = idx % 30;
    double ph = -2.0 * DPI * (double)mp * j / 30.0;
    double s, c; sincos(ph, &s, &c);
    gPH30[idx] = make_float2((float)c, (float)s); return;
  }
  idx -= 570;
  if (idx < 380) {
    int m = idx / 20 - 9, a = idx % 20;
    double ph = (double)m * 2.0 * DPI * a / 20.0;
    double s, c; sincos(ph, &s, &c);
    gEA1[idx] = make_float2((float)c, (float)s); return;
  }
  idx -= 380;
  if (idx < 132) {
    int m = idx / 12 - 5, a = idx % 12;
    double ph = (double)m * 2.0 * DPI * a / 12.0;
    double s, c; sincos(ph, &s, &c);
    gEA2[idx] = make_float2((float)c, (float)s); return;
  }
  idx -= 132;
  if (idx < 220) {
    int mu = idx / 20 - 5, a = idx % 20;
    double ph = -2.0 * DPI * (double)mu * a / 20.0;
    double s, c; sincos(ph, &s, &c);
    gF20[idx] = make_float2((float)c, (float)s); return;
  }
  idx -= 220;
  if (idx < 1650) {
    int kb = idx / 55, j = idx % 55;
    int l = 0; while (j >= l + 1) { j -= l + 1; ++l; }
    int mm = j;
    double beta = DPI * (2*kb + 1) / 60.0;
    double v = wigd(l, mm, 0, beta) * quadw(15, kb);
    gWS2F[(l*19 + 9 + mm)*30 + kb] = (float)v;
    gWS2F[(l*19 + 9 - mm)*30 + kb] = (mm & 1) ? (float)(-v) : (float)v;
    return;
  }
  idx -= 1650;
  if (idx < 165) {
    int ib = idx / 55, j = idx % 55;
    int l = 0; while (j >= l + 1) { j -= l + 1; ++l; }
    int mm = j;
    double beta = (ib + 1) * DPI / 24.0;
    gDS2G[(ib*10 + l)*10 + mm] = (float)wigd(l, mm, 0, beta);
    return;
  }
  idx -= 165;
  if (idx < 7700) {
    int k = idx / 385, j = idx % 385;
    int l = 0; while (j >= (l+1)*(l+1)) { j -= (l+1)*(l+1); ++l; }
    int mm = (int)sqrtf((float)j);
    while (mm*mm > j) --mm;
    while ((mm+1)*(mm+1) <= j) ++mm;
    int nn = j - mm*mm - mm;
    double beta = DPI * (2*k + 1) / 40.0;
    float fv = (float)(wigd(l, mm, nn, beta) * (2*l + 1));
    float sv = ((mm - nn) & 1) ? -fv : fv;
    float* W = &gWINV1[(k*10 + l)*361];
    W[(9+mm)*19 + (9+nn)] = fv;
    W[(9+nn)*19 + (9+mm)] = sv;
    W[(9-mm)*19 + (9-nn)] = sv;
    W[(9-nn)*19 + (9-mm)] = fv;
    return;
  }
  idx -= 7700;
  if (idx < 1092) {
    int k = idx / 91, j = idx % 91;
    int l = 0; while (j >= (l+1)*(l+1)) { j -= (l+1)*(l+1); ++l; }
    int mm = (int)sqrtf((float)j);
    while (mm*mm > j) --mm;
    while ((mm+1)*(mm+1) <= j) ++mm;
    int nn = j - mm*mm - mm;
    double beta = DPI * (2*k + 1) / 24.0;
    float fv = (float)(wigd(l, mm, nn, beta) * (2*l + 1));
    float sv = ((mm - nn) & 1) ? -fv : fv;
    float* W = &gWINV2[(k*6 + l)*121];
    W[(5+mm)*11 + (5+nn)] = fv;
    W[(5+nn)*11 + (5+mm)] = sv;
    W[(5-mm)*11 + (5-nn)] = sv;
    W[(5-nn)*11 + (5-mm)] = fv;
    return;
  }
  idx -= 1092;
  if (idx < 273) {
    int ib = idx / 91, j = idx % 91;
    int l = 0; while (j >= (l+1)*(l+1)) { j -= (l+1)*(l+1); ++l; }
    int mm = (int)sqrtf((float)j);
    while (mm*mm > j) --mm;
    while ((mm+1)*(mm+1) <= j) ++mm;
    int nn = j - mm*mm - mm;
    double beta = (ib + 1) * DPI / 24.0;
    float fv = (float)wigd(l, mm, nn, beta);
    float sv = ((mm - nn) & 1) ? -fv : fv;
    float* W = &gDG3[(ib*6 + l)*121];
    W[(5+mm)*11 + (5+nn)] = fv;
    W[(5+nn)*11 + (5+mm)] = sv;
    W[(5-mm)*11 + (5-nn)] = sv;
    W[(5-nn)*11 + (5-mm)] = fv;
  }
}

__global__ void k_init_fill() {
  const int TOT = 4560 + 14520 + 104544 + 171000;
  for (int idx = blockIdx.x * blockDim.x + threadIdx.x; idx < TOT;
       idx += gridDim.x * blockDim.x) {
    int r = idx;
    if (r < 4560) {
      int p = r / 190, lm = r % 190, l = lm / 19, m = lm % 19, mp = m - 9;
      float2 v = make_float2(0.f, 0.f);
      if (abs(mp) <= l) {
        int ib = p / 8, ia = p % 8;
        float d;
        if (mp >= 0) d = gDS2G[(ib*10 + l)*10 + mp];
        else {
          d = gDS2G[(ib*10 + l)*10 - mp];
          if ((-mp) & 1) d = -d;
        }
        float2 ph = gPA8[ia*19 + 9 + mp];
        v = make_float2(d * ph.x, d * ph.y);
      }
      gBS2[r] = v; continue;
    }
    r -= 4560;
    if (r < 14520) {
      int k = r / 726, l = (r / 121) % 6, m = (r / 11) % 11, n = r % 11;
      float w = gWINV1[(k*10 + l)*361 + (m + 4)*19 + (n + 4)];
      gWSO3[r] = w * gQW10[k] / (float)(2*l + 1); continue;
    }
    r -= 14520;
    if (r < 104544) {
      int p = r / 726, l = (r / 121) % 6, m = (r / 11) % 11, n = r % 11;
      int ib = p / 48, ia = (p / 6) % 8, ig = p % 6;
      float d = gDG3[(ib*6 + l)*121 + m*11 + n];
      float2 pa = gPA8b[ia*11 + m], pg = gPG6[ig*11 + n];
      float2 ph = make_float2(pa.x*pg.x - pa.y*pg.y, pa.x*pg.y + pa.y*pg.x);
      gBSO3[r] = make_float2(d * ph.x, d * ph.y); continue;
    }
    r -= 104544;
    {
      int lm = r / 900, kj = r % 900;
      int k = kj / 30, j = kj % 30;
      int mp = (lm % 19) - 9;
      float w = gWS2F[lm*30 + k];
      float2 ph = gPH30[(mp + 9)*30 + j];
      gT1t[kj*190 + lm] = make_float2(w * ph.x, w * ph.y);
    }
  }
}

// ======================= pipeline =======================
__global__ void k_x_part(const float* __restrict__ x) {
  __shared__ float xs[XLEN];
  int blk = blockIdx.x;
  int c = blk % XCH, b = blk / XCH;
  for (int i = threadIdx.x; i < XLEN; i += blockDim.x) xs[i] = x[b*900 + c*XLEN + i];
  __syncthreads();
  int t = threadIdx.x;
  if (t < 190) {
    float re = 0.f, im = 0.f;
    const float2* T = &gT1t[c * XLEN * 190];
#pragma unroll 5
    for (int i = 0; i < XLEN; ++i) {
      float xv = xs[i];
      float2 w = T[i * 190 + t];
      re += xv * w.x; im += xv * w.y;
    }
    gXpart[c][b*190 + t] = make_float2(re, im);
  }
}

__global__ void k_comb_psi(const float* __restrict__ k1) {
  int idx = blockIdx.x * blockDim.x + threadIdx.x;
  if (idx < NB*190) {
    float re = 0.f, im = 0.f;
#pragma unroll
    for (int c = 0; c < XCH; ++c) {
      float2 v = gXpart[c][idx];
      re += v.x; im += v.y;
    }
    gX[idx] = make_float2(re, im);
    return;
  }
  idx -= NB*190;
  if (idx < FF1*190) {
    int lm = idx % 190, o = idx / 190;
    float re = 0.f, im = 0.f;
    for (int p = 0; p < P1; ++p) {
      float kv = k1[o*P1 + p];
      float2 bv = gBS2[p*190 + lm];
      re += kv * bv.x; im += kv * bv.y;
    }
    gPSI[idx] = make_float2(re, im);
  }
}

// ---- fused stage 1: 5 k/block, folds + register-cached DFT ----
__global__ __launch_bounds__(256) void k_fused1() {
  __shared__ float2 sX[190];
  __shared__ float2 sP[190];
  __shared__ float2 sEA1[380];
  __shared__ float2 sF20[220];
  __shared__ float2 sFH[950];
  __shared__ float2 sT[1000];
  __shared__ float  sY[2000];
  __shared__ float2 sU[600];

  int blk = blockIdx.x;                 // (b*FF1 + o)*4 + kp
  int kp = blk % 4;
  int bo = blk / 4;
  int o = bo % FF1, b = bo / FF1;
  int k0 = kp * 5;
  int tid = threadIdx.x;

  for (int e = tid; e < 190; e += 256) { sX[e] = gX[b*190 + e]; sP[e] = gPSI[o*190 + e]; }
  for (int e = tid; e < 380; e += 256) sEA1[e] = gEA1[e];
  for (int e = tid; e < 220; e += 256) sF20[e] = gF20[e];
  __syncthreads();

  for (int e = tid; e < 950; e += 256) {
    int sk = e / 190, r = e % 190;
    int mi = r / 19, n = r % 19;
    int an = n - 9; if (an < 0) an = -an;
    int lmin = mi > an ? mi : an;
    const float* W = &gWINV1[(k0 + sk) * BB1 * 361];
    int off = (9 + mi)*19 + n;
    float re = 0.f, im = 0.f;
    for (int l = lmin; l < BB1; ++l) {
      float w = W[l*361 + off];
      float2 xm = sX[l*19 + 9 + mi];
      float2 pe = sP[l*19 + n];
      re += w * (xm.x * pe.x + xm.y * pe.y);
      im += w * (xm.y * pe.x - xm.x * pe.y);
    }
    sFH[e] = make_float2(re, im);
  }
  __syncthreads();

  if (tid < 250) {
    int sk = tid / 50, rem = tid % 50;
    int mi = rem / 5, gq = rem % 5;
    float2 f[19];
#pragma unroll
    for (int n = 0; n < 19; ++n) f[n] = sFH[sk*190 + mi*19 + n];
#pragma unroll
    for (int dg = 0; dg < 2; ++dg) {
      int g = gq*2 + dg;
      float sex = 0.f, sey = 0.f, sox = 0.f, soy = 0.f;
#pragma unroll
      for (int n = 0; n < 19; ++n) {
        float2 ea = sEA1[n*20 + g];
        float tx = f[n].x * ea.x - f[n].y * ea.y;
        float ty = f[n].x * ea.y + f[n].y * ea.x;
        if (n & 1) { sex += tx; sey += ty; }
        else       { sox += tx; soy += ty; }
      }
      sT[sk*200 + mi*20 + g]      = make_float2(sex + sox, sey + soy);
      sT[sk*200 + mi*20 + g + 10] = make_float2(sex - sox, sey - soy);
    }
  }
  __syncthreads();

  if (tid < 200) {
    int sk = tid / 40, rem = tid % 40;
    int g = rem / 2, ah = rem % 2;
    float t0 = sT[sk*200 + g].x;
    float2 tm[9];
#pragma unroll
    for (int mm = 1; mm < 10; ++mm) tm[mm-1] = sT[sk*200 + mm*20 + g];
    int a0 = ah * 5;
#pragma unroll
    for (int da = 0; da < 5; ++da) {
      int a = a0 + da;
      float se = 0.f, so = 0.f;
#pragma unroll
      for (int mm = 1; mm < 10; ++mm) {
        float2 ea = sEA1[(9 + mm)*20 + a];
        float v = tm[mm-1].x * ea.x - tm[mm-1].y * ea.y;
        if (mm & 1) so += v; else se += v;
      }
      float y1 = t0 + 2.f * (se + so);
      float y2v = t0 + 2.f * (se - so);
      y1 = (y1 > 0.f) ? y1 : 0.f;
      y2v = (y2v > 0.f) ? y2v : 0.f;
      sY[sk*400 + a*20 + g]      = y1 + y2v;
      sY[sk*400 + (a+10)*20 + g] = y1 - y2v;
    }
  }
  __syncthreads();

  if (tid < 100) {
    int sk = tid / 20, g = tid % 20;
    float ys[10], yd[10];
#pragma unroll
    for (int a = 0; a < 10; ++a) {
      ys[a] = sY[sk*400 + a*20 + g];
      yd[a] = sY[sk*400 + (a+10)*20 + g];
    }
#pragma unroll
    for (int r = 0; r < 6; ++r) {
      const float* yb = (r & 1) ? yd : ys;
      float re = 0.f, im = 0.f;
#pragma unroll
      for (int a = 0; a < 10; ++a) {
        float2 fw = sF20[(5 + r)*20 + a];
        re += yb[a] * fw.x; im += yb[a] * fw.y;
      }
      sU[sk*120 + r*20 + g] = make_float2(re, im);
    }
  }
  __syncthreads();

  // ymn wedge only (mu >= 5); mirror write dropped (dead downstream)
  for (int e = tid; e < 330; e += 256) {
    int sk = e / 66, rr = e % 66;
    int r = rr / 11, nu = rr % 11;
    float sgn = (nu & 1) ? 1.f : -1.f;
    float re = 0.f, im = 0.f;
#pragma unroll
    for (int g = 0; g < 10; ++g) {
      float2 u1 = sU[sk*120 + r*20 + g];
      float2 u2 = sU[sk*120 + r*20 + g + 10];
      float ux = u1.x + sgn * u2.x;
      float uy = u1.y + sgn * u2.y;
      float2 f = sF20[nu*20 + g];
      re += ux * f.x - uy * f.y;
      im += ux * f.y + uy * f.x;
    }
    long yb = ((long)bo * 20 + k0 + sk) * 121;
    gYMN[yb + (5 + r)*11 + nu] = make_float2(re, im);
  }
}

// X2 wedge: one thread per (b,c,we), we over mu=5..10 x nu=0..10 (66 positions).
__global__ void k_x2() {
  int idx = blockIdx.x * blockDim.x + threadIdx.x;
  if (idx >= NB*FF1*66) return;
  int we = idx % 66, bc = idx / 66;
  int mn = (5 + we / 11)*11 + (we % 11);
  float2 ym[20];
  long ybase = (long)bc * 20 * 121 + mn;
#pragma unroll
  for (int k = 0; k < 20; ++k) ym[k] = gYMN[ybase + k*121];
  long xbase = (long)bc * 726 + mn;
#pragma unroll
  for (int l = 0; l < BB2; ++l) {
    float re = 0.f, im = 0.f;
#pragma unroll
    for (int k = 0; k < 20; ++k) {
      float w = gWSO3[(k*6 + l)*121 + mn];
      re += w * ym[k].x; im += w * ym[k].y;
    }
    gX2[xbase + l*121] = make_float2(re, im);
  }
}

// psi2 as real x complex GEMM: (800 x 144) x (144 x 726)
__global__ void k_psi2(const float* __restrict__ k2) {
  const int M = 800, N = 726, K = 144;
  __shared__ float As[32][17];
  __shared__ __align__(16) float2 Bs[16][34];
  int tx = threadIdx.x, ty = threadIdx.y;
  int tid = ty * 16 + tx;
  int row0 = blockIdx.y * 32, col0 = blockIdx.x * 32;
  float2 c00 = {0.f,0.f}, c01 = {0.f,0.f}, c10 = {0.f,0.f}, c11 = {0.f,0.f};

  for (int kt = 0; kt < K; kt += 16) {
#pragma unroll
    for (int e = tid; e < 512; e += 256) {
      int i = e >> 4, kq = e & 15;
      int row = row0 + i, kc = kt + kq;
      As[i][kq] = (row < M) ? k2[row*K + kc] : 0.f;
    }
#pragma unroll
    for (int e = tid; e < 512; e += 256) {
      int kq = e >> 5, j = e & 31;
      int kc = kt + kq, col = col0 + j;
      Bs[kq][j] = (col < N) ? gBSO3[kc*726 + col] : make_float2(0.f, 0.f);
    }
    __syncthreads();
#pragma unroll
    for (int kq = 0; kq < 16; ++kq) {
      float a0 = As[ty*2][kq];
      float a1 = As[ty*2 + 1][kq];
      float4 bb = *reinterpret_cast<const float4*>(&Bs[kq][tx*2]);
      c00.x += a0*bb.x; c00.y += a0*bb.y;
      c01.x += a0*bb.z; c01.y += a0*bb.w;
      c10.x += a1*bb.x; c10.y += a1*bb.y;
      c11.x += a1*bb.z; c11.y += a1*bb.w;
    }
    __syncthreads();
  }
  int r0 = row0 + ty*2, cc0 = col0 + tx*2;
  if (r0 < M) {
    if (cc0 < N)     gPSI2[r0*726 + cc0] = c00;
    if (cc0 + 1 < N) gPSI2[r0*726 + cc0 + 1] = c01;
  }
  if (r0 + 1 < M) {
    if (cc0 < N)     gPSI2[(r0+1)*726 + cc0] = c10;
    if (cc0 + 1 < N) gPSI2[(r0+1)*726 + cc0 + 1] = c11;
  }
}

// Z2 complex GEMM per l; rows restricted to m >= center.
__global__ void k_z2() {
  int l = blockIdx.z;
  int D = 2*l + 1;
  int E = l + 1;
  int R = 128*E, C = 40*D, K = 20*D;
  int row0 = blockIdx.y * 32, col0 = blockIdx.x * 64;
  if (row0 >= R || col0 >= C) return;
  __shared__ __align__(16) float2 As[32][17];
  __shared__ __align__(16) float2 Bs[16][66];
  __shared__ int sRA[32];
  __shared__ int sCB[64];
  __shared__ int sRO[32];
  __shared__ int sCO[64];
  __shared__ int sKA[220];
  __shared__ int sKB[220];
  int tx = threadIdx.x, ty = threadIdx.y;
  int tid = ty * 16 + tx;
  int base = 5 - l;
  int L0 = l*121 + base*12;

  for (int e = tid; e < 32; e += 256) {
    int row = row0 + e;
    if (row < R) {
      int b = row / E, mi = row - b*E;
      int rp = l*121 + (5 + mi)*11 + base;
      sRA[e] = b*14520 + rp;
      sRO[e] = b*29040 + rp;
    } else { sRA[e] = -1; sRO[e] = -1; }
  }
  for (int e = tid; e < 64; e += 256) {
    int col = col0 + e;
    if (col < C) {
      int o = col / D, ni = col - o*D;
      sCB[e] = o*726 + ni*11 + L0;
      sCO[e] = o*726 + ni;
    } else { sCB[e] = -1; sCO[e] = -1; }
  }
  for (int e = tid; e < K; e += 256) {
    int ii = e / D, ki = e - ii*D;
    sKA[e] = ii*726 + ki;
    sKB[e] = ii*29040 + ki;
  }
  __syncthreads();

  float2 acc[2][4];
#pragma unroll
  for (int i = 0; i < 2; ++i)
#pragma unroll
    for (int j = 0; j < 4; ++j) acc[i][j] = make_float2(0.f, 0.f);

  for (int kt = 0; kt < K; kt += 16) {
#pragma unroll
    for (int e = tid; e < 512; e += 256) {
      int i = e >> 4, kq = e & 15;
      int kc = kt + kq;
      float2 v = make_float2(0.f, 0.f);
      if (kc < K && sRA[i] >= 0) v = gX2[sRA[i] + sKA[kc]];
      As[i][kq] = v;
    }
#pragma unroll
    for (int e = tid; e < 1024; e += 256) {
      int kq = e >> 6, j = e & 63;
      int kc = kt + kq;
      float2 v = make_float2(0.f, 0.f);
      if (kc < K && sCB[j] >= 0) v = gPSI2[sCB[j] + sKB[kc]];
      Bs[kq][j] = v;
    }
    __syncthreads();
#pragma unroll
    for (int kq = 0; kq < 16; ++kq) {
      float2 a0 = As[ty*2][kq];
      float2 a1 = As[ty*2 + 1][kq];
      float4 b0 = *reinterpret_cast<const float4*>(&Bs[kq][tx*2]);
      float4 b1 = *reinterpret_cast<const float4*>(&Bs[kq][tx*2 + 32]);
      acc[0][0].x += a0.x*b0.x + a0.y*b0.y;  acc[0][0].y += a0.y*b0.x - a0.x*b0.y;
      acc[0][1].x += a0.x*b0.z + a0.y*b0.w;  acc[0][1].y += a0.y*b0.z - a0.x*b0.w;
      acc[0][2].x += a0.x*b1.x + a0.y*b1.y;  acc[0][2].y += a0.y*b1.x - a0.x*b1.y;
      acc[0][3].x += a0.x*b1.z + a0.y*b1.w;  acc[0][3].y += a0.y*b1.z - a0.x*b1.w;
      acc[1][0].x += a1.x*b0.x + a1.y*b0.y;  acc[1][0].y += a1.y*b0.x - a1.x*b0.y;
      acc[1][1].x += a1.x*b0.z + a1.y*b0.w;  acc[1][1].y += a1.y*b0.z - a1.x*b0.w;
      acc[1][2].x += a1.x*b1.x + a1.y*b1.y;  acc[1][2].y += a1.y*b1.x - a1.x*b1.y;
      acc[1][3].x += a1.x*b1.z + a1.y*b1.w;  acc[1][3].y += a1.y*b1.z - a1.x*b1.w;
    }
    __syncthreads();
  }

  int ir0 = ty*2;
  int jc[4] = { tx*2, tx*2 + 1, tx*2 + 32, tx*2 + 33 };
#pragma unroll
  for (int dr = 0; dr < 2; ++dr) {
    int ro = sRO[ir0 + dr];
    if (ro < 0) continue;
#pragma unroll
    for (int dc = 0; dc < 4; ++dc) {
      int co = sCO[jc[dc]];
      if (co < 0) continue;
      gZ2[ro + co] = acc[dr][dc];
    }
  }
}

// ---- fused stage 2: wedge-only sZ loads, hermitian + folds ----
__global__ __launch_bounds__(256) void k_fused2() {
  __shared__ float2 sZw[396];
  __shared__ float2 sFH2[792];
  __shared__ float2 sT2[864];
  __shared__ float2 sEA2[132];
  __shared__ float  sRed[256];

  int blk = blockIdx.x;
  int tid = threadIdx.x;

  for (int e = tid; e < 396; e += 256) {
    int l = e / 66, rr = e % 66;
    sZw[e] = gZ2[(long)blk * 726 + l*121 + (5 + rr/11)*11 + (rr % 11)];
  }
  for (int e = tid; e < 132; e += 256) sEA2[e] = gEA2[e];
  __syncthreads();

  for (int e = tid; e < 792; e += 256) {
    int k = e / 66, rem = e % 66;
    int mi = rem / 11, n = rem % 11;
    int an = n - 5; if (an < 0) an = -an;
    int lmin = mi > an ? mi : an;
    float re = 0.f, im = 0.f;
    for (int l = lmin; l < BB2; ++l) {
      float w = gWINV2[(k*6 + l)*121 + (5 + mi)*11 + n];
      float2 z = sZw[l*66 + mi*11 + n];
      re += w * z.x; im += w * z.y;
    }
    sFH2[e] = make_float2(re, im);
  }
  __syncthreads();

  for (int e = tid; e < 216; e += 256) {
    int k = e / 18, rr = e % 18;
    int mi = rr / 3, gh = rr % 3;
    float2 f[11];
#pragma unroll
    for (int n = 0; n < 11; ++n) f[n] = sFH2[(k*6 + mi)*11 + n];
#pragma unroll
    for (int dg = 0; dg < 2; ++dg) {
      int g = gh*2 + dg;
      float sex = 0.f, sey = 0.f, sox = 0.f, soy = 0.f;
#pragma unroll
      for (int n = 0; n < 11; ++n) {
        float2 ea = sEA2[n*12 + g];
        float tx = f[n].x * ea.x - f[n].y * ea.y;
        float ty = f[n].x * ea.y + f[n].y * ea.x;
        if (n & 1) { sex += tx; sey += ty; }
        else       { sox += tx; soy += ty; }
      }
      sT2[(k*6 + mi)*12 + g]     = make_float2(sex + sox, sey + soy);
      sT2[(k*6 + mi)*12 + g + 6] = make_float2(sex - sox, sey - soy);
    }
  }
  __syncthreads();

  float partial = 0.f;
  for (int e = tid; e < 144; e += 256) {
    int k = e / 12, g = e % 12;
    float t0 = sT2[k*72 + g].x;
    float2 tm[5];
#pragma unroll
    for (int mm = 1; mm < 6; ++mm) tm[mm-1] = sT2[(k*6 + mm)*12 + g];
    float wk = gWINT[k];
#pragma unroll
    for (int a = 0; a < 6; ++a) {
      float se = 0.f, so = 0.f;
#pragma unroll
      for (int mm = 1; mm < 6; ++mm) {
        float2 ea = sEA2[(5 + mm)*12 + a];
        float v = tm[mm-1].x * ea.x - tm[mm-1].y * ea.y;
        if (mm & 1) so += v; else se += v;
      }
      float v1 = t0 + 2.f * (se + so);
      float v2 = t0 + 2.f * (se - so);
      v1 = (v1 > 0.f) ? v1 : 0.f;
      v2 = (v2 > 0.f) ? v2 : 0.f;
      partial += (v1 + v2) * wk;
    }
  }
  sRed[tid] = partial;
  __syncthreads();
  for (int s = 128; s > 0; s >>= 1) {
    if (tid < s) sRed[tid] += sRed[tid + s];
    __syncthreads();
  }
  if (tid == 0) gFEAT[blk] = sRed[0] / 144.0f;
}

__global__ void k_out(const float* __restrict__ wl, const float* __restrict__ bl,
                      float* __restrict__ out) {
  int idx = blockIdx.x * blockDim.x + threadIdx.x;
  if (idx >= NB*FOUT) return;
  int f = idx % FOUT, b = idx / FOUT;
  float acc = bl[f];
#pragma unroll
  for (int o = 0; o < FF2; ++o) acc += gFEAT[b*FF2 + o] * wl[f*FF2 + o];
  out[idx] = acc;
}

extern "C" void kernel_launch(void* const* d_in, const int* in_sizes, int n_in,
                              void* d_out, int out_size) {
  const float* x  = (const float*)d_in[0];
  const float* k1 = (const float*)d_in[1];
  const float* k2 = (const float*)d_in[2];
  const float* wl = (const float*)d_in[3];
  const float* bl = (const float*)d_in[4];
  float* out = (float*)d_out;

  k_init_wig<<<(12520 + 255) / 256, 256>>>();
  k_init_fill<<<(294624 + 255) / 256, 256>>>();

  k_x_part<<<NB*XCH, 192>>>(x);
  k_comb_psi<<<(NB*190 + FF1*190 + 255) / 256, 256>>>(k1);
  k_fused1<<<NB*FF1*4, 256>>>();
  k_x2 <<<(NB*FF1*66 + 255) / 256, 256>>>();
  k_psi2<<<dim3((726 + 31) / 32, (800 + 31) / 32), dim3(16, 16)>>>(k2);
  k_z2<<<dim3(7, 24, 6), dim3(16, 16)>>>();
  k_fused2<<<NB*FF2, 256>>>();
  k_out<<<(NB*FOUT + 255) / 256, 256>>>(wl, bl, out);
}